// round 13
// baseline (speedup 1.0000x reference)
#include <cuda_runtime.h>
#include <cstdint>

// DownscaleLabel: label [8,1024,1024] int32 in {-1,0..6} -> out [8,1,64,64] f32.
// Per 16x16 tile: 8-class histogram (ignore -1 -> class 7 via &7), first-max
// argmax, -1 if argmax==7 or max_count < 192 (== ratio < 0.75, exact).
//
// Final form (empirical optimum across 6 designs; platform delivers ~3.5TB/s
// for this burst regardless of mechanism). 1 warp = 8 adjacent tiles.
// Lane l: tile = l>>2, quad = l&3 (one int4 column), all 16 tile rows;
// each warp load = contiguous 512B. All 16 int4 loads front-batched
// (64 data regs, true MLP=16, enabled by __launch_bounds__(256,3)).
// Histogram: nibble phases (max 8/field) widened into byte accs
// e=(c0,c2,c4,c6), o=(c1,c3,c5,c7), max 64/byte. Reduce over 4 quad lanes:
// xor1 in bytes (max 128), widen to 16-bit fields, xor2 (max 256).
// Lanes quad==0 emit 8 tiles in parallel.

static constexpr int SCALE = 16;
static constexpr int TILES_PER_IMG = 64 * 64;            // 4096
static constexpr int WARPS_PER_IMG = TILES_PER_IMG / 8;  // 512

__global__ void __launch_bounds__(256, 3)
downscale_label_kernel(const int* __restrict__ label,
                       float* __restrict__ out,
                       int n_warps) {
    const int wg   = (blockIdx.x * blockDim.x + threadIdx.x) >> 5;
    const int lane = threadIdx.x & 31;
    if (wg >= n_warps) return;

    const int b   = wg >> 9;                    // / WARPS_PER_IMG (512)
    const int wi  = wg & (WARPS_PER_IMG - 1);
    const int th  = wi >> 3;                    // tile row (64), 8 warps/row
    const int twg = wi & 7;                     // group of 8 tiles

    // int4 index: image row = 256 int4; warp covers 32 consecutive int4.
    const int4* p = reinterpret_cast<const int4*>(label)
                    + ((size_t)b << 18)                 // b * 1M px / 4
                    + ((size_t)th << 12)                // th * 16 rows * 256
                    + (twg << 5) + lane;

    // Front-batch ALL 16 loads (64 data regs) -> MLP = 16.
    const int4 v0  = __ldg(p);
    const int4 v1  = __ldg(p + 1 * 256);
    const int4 v2  = __ldg(p + 2 * 256);
    const int4 v3  = __ldg(p + 3 * 256);
    const int4 v4  = __ldg(p + 4 * 256);
    const int4 v5  = __ldg(p + 5 * 256);
    const int4 v6  = __ldg(p + 6 * 256);
    const int4 v7  = __ldg(p + 7 * 256);
    const int4 v8  = __ldg(p + 8 * 256);
    const int4 v9  = __ldg(p + 9 * 256);
    const int4 v10 = __ldg(p + 10 * 256);
    const int4 v11 = __ldg(p + 11 * 256);
    const int4 v12 = __ldg(p + 12 * 256);
    const int4 v13 = __ldg(p + 13 * 256);
    const int4 v14 = __ldg(p + 14 * 256);
    const int4 v15 = __ldg(p + 15 * 256);

    // Byte histograms: e = classes (0,2,4,6), o = (1,3,5,7). Max 64/byte.
    unsigned e = 0u, o = 0u;

#define HPHASE(a, c)                                            \
    {                                                           \
        unsigned n = 0u;                                        \
        n += 1u << (((unsigned)(a).x & 7u) << 2);               \
        n += 1u << (((unsigned)(a).y & 7u) << 2);               \
        n += 1u << (((unsigned)(a).z & 7u) << 2);               \
        n += 1u << (((unsigned)(a).w & 7u) << 2);               \
        n += 1u << (((unsigned)(c).x & 7u) << 2);               \
        n += 1u << (((unsigned)(c).y & 7u) << 2);               \
        n += 1u << (((unsigned)(c).z & 7u) << 2);               \
        n += 1u << (((unsigned)(c).w & 7u) << 2);               \
        e += n & 0x0F0F0F0Fu;                                   \
        o += (n >> 4) & 0x0F0F0F0Fu;                            \
    }

    HPHASE(v0, v1)
    HPHASE(v2, v3)
    HPHASE(v4, v5)
    HPHASE(v6, v7)
    HPHASE(v8, v9)
    HPHASE(v10, v11)
    HPHASE(v12, v13)
    HPHASE(v14, v15)
#undef HPHASE

    // Reduce over the 4 quad lanes of each tile.
    e += __shfl_xor_sync(0xffffffffu, e, 1);   // max 128, bytes still safe
    o += __shfl_xor_sync(0xffffffffu, o, 1);
    // Widen byte fields -> 16-bit fields for the final (max 256) round.
    unsigned e_lo = e & 0x00FF00FFu;           // [c0 | c4<<16]
    unsigned e_hi = (e >> 8) & 0x00FF00FFu;    // [c2 | c6<<16]
    unsigned o_lo = o & 0x00FF00FFu;           // [c1 | c5<<16]
    unsigned o_hi = (o >> 8) & 0x00FF00FFu;    // [c3 | c7<<16]
    e_lo += __shfl_xor_sync(0xffffffffu, e_lo, 2);
    e_hi += __shfl_xor_sync(0xffffffffu, e_hi, 2);
    o_lo += __shfl_xor_sync(0xffffffffu, o_lo, 2);
    o_hi += __shfl_xor_sync(0xffffffffu, o_hi, 2);

    if ((lane & 3) == 0) {
        int counts[8];
        counts[0] = e_lo & 0xFFFF;  counts[4] = e_lo >> 16;
        counts[2] = e_hi & 0xFFFF;  counts[6] = e_hi >> 16;
        counts[1] = o_lo & 0xFFFF;  counts[5] = o_lo >> 16;
        counts[3] = o_hi & 0xFFFF;  counts[7] = o_hi >> 16;

        int best = counts[0], arg = 0;
#pragma unroll
        for (int i = 1; i < 8; ++i) {
            if (counts[i] > best) { best = counts[i]; arg = i; }  // first-max
        }
        // ratio < 0.75  <=>  count < 192 (0.75 * 256 == 192 exactly)
        const int res = (arg == 7 || best < 192) ? -1 : arg;

        const int tw = (twg << 3) + (lane >> 2);
        out[b * TILES_PER_IMG + th * 64 + tw] = (float)res;
    }
}

extern "C" void kernel_launch(void* const* d_in, const int* in_sizes, int n_in,
                              void* d_out, int out_size) {
    const int* label = (const int*)d_in[0];
    float* out = (float*)d_out;

    // 8M px / 256 px per tile / 8 tiles per warp = 4096 warps.
    const int n_tiles = in_sizes[0] / (SCALE * SCALE);
    const int n_warps = n_tiles / 8;

    const int threads = 256;                 // 8 warps/block -> 512 blocks
    const int blocks = (n_warps * 32 + threads - 1) / threads;

    downscale_label_kernel<<<blocks, threads>>>(label, out, n_warps);
}

// round 14
// speedup vs baseline: 1.0449x; 1.0449x over previous
#include <cuda_runtime.h>
#include <cstdint>

// DownscaleLabel: label [8,1024,1024] int32 in {-1,0..6} -> out [8,1,64,64] f32.
// Per 16x16 tile: 8-class histogram (ignore -1 -> class 7 via &7), first-max
// argmax, -1 if argmax==7 or max_count < 192 (== ratio < 0.75, exact).
//
// Converged config (measured 8.704us, fastest of 8 designs; platform delivers
// ~3.5TB/s for this burst regardless of mechanism — LDG / prefetch / TMA all
// equal). 1 warp = 8 horizontally-adjacent tiles. Lane l: tile = l>>2,
// quad = l&3 (one int4 column), all 16 tile rows; each warp load = contiguous
// 512B. All 16 int4 loads front-batched (64 data regs, true MLP=16, enabled
// by __launch_bounds__(128,4)). Histogram: nibble phases (max 8/field)
// widened into byte accs e=(c0,c2,c4,c6), o=(c1,c3,c5,c7), max 64/byte.
// Reduce over 4 quad lanes: xor1 in bytes (max 128), widen to 16-bit fields,
// xor2 (max 256). Lanes quad==0 emit 8 tiles in parallel.

static constexpr int SCALE = 16;
static constexpr int TILES_PER_IMG = 64 * 64;            // 4096
static constexpr int WARPS_PER_IMG = TILES_PER_IMG / 8;  // 512

__global__ void __launch_bounds__(128, 4)
downscale_label_kernel(const int* __restrict__ label,
                       float* __restrict__ out,
                       int n_warps) {
    const int wg   = (blockIdx.x * blockDim.x + threadIdx.x) >> 5;
    const int lane = threadIdx.x & 31;
    if (wg >= n_warps) return;

    const int b   = wg >> 9;                    // / WARPS_PER_IMG (512)
    const int wi  = wg & (WARPS_PER_IMG - 1);
    const int th  = wi >> 3;                    // tile row (64), 8 warps/row
    const int twg = wi & 7;                     // group of 8 tiles

    // int4 index: image row = 256 int4; warp covers 32 consecutive int4.
    const int4* p = reinterpret_cast<const int4*>(label)
                    + ((size_t)b << 18)                 // b * 1M px / 4
                    + ((size_t)th << 12)                // th * 16 rows * 256
                    + (twg << 5) + lane;

    // Front-batch ALL 16 loads (64 data regs) -> MLP = 16.
    const int4 v0  = __ldg(p);
    const int4 v1  = __ldg(p + 1 * 256);
    const int4 v2  = __ldg(p + 2 * 256);
    const int4 v3  = __ldg(p + 3 * 256);
    const int4 v4  = __ldg(p + 4 * 256);
    const int4 v5  = __ldg(p + 5 * 256);
    const int4 v6  = __ldg(p + 6 * 256);
    const int4 v7  = __ldg(p + 7 * 256);
    const int4 v8  = __ldg(p + 8 * 256);
    const int4 v9  = __ldg(p + 9 * 256);
    const int4 v10 = __ldg(p + 10 * 256);
    const int4 v11 = __ldg(p + 11 * 256);
    const int4 v12 = __ldg(p + 12 * 256);
    const int4 v13 = __ldg(p + 13 * 256);
    const int4 v14 = __ldg(p + 14 * 256);
    const int4 v15 = __ldg(p + 15 * 256);

    // Byte histograms: e = classes (0,2,4,6), o = (1,3,5,7). Max 64/byte.
    unsigned e = 0u, o = 0u;

#define HPHASE(a, c)                                            \
    {                                                           \
        unsigned n = 0u;                                        \
        n += 1u << (((unsigned)(a).x & 7u) << 2);               \
        n += 1u << (((unsigned)(a).y & 7u) << 2);               \
        n += 1u << (((unsigned)(a).z & 7u) << 2);               \
        n += 1u << (((unsigned)(a).w & 7u) << 2);               \
        n += 1u << (((unsigned)(c).x & 7u) << 2);               \
        n += 1u << (((unsigned)(c).y & 7u) << 2);               \
        n += 1u << (((unsigned)(c).z & 7u) << 2);               \
        n += 1u << (((unsigned)(c).w & 7u) << 2);               \
        e += n & 0x0F0F0F0Fu;                                   \
        o += (n >> 4) & 0x0F0F0F0Fu;                            \
    }

    HPHASE(v0, v1)
    HPHASE(v2, v3)
    HPHASE(v4, v5)
    HPHASE(v6, v7)
    HPHASE(v8, v9)
    HPHASE(v10, v11)
    HPHASE(v12, v13)
    HPHASE(v14, v15)
#undef HPHASE

    // Reduce over the 4 quad lanes of each tile.
    e += __shfl_xor_sync(0xffffffffu, e, 1);   // max 128, bytes still safe
    o += __shfl_xor_sync(0xffffffffu, o, 1);
    // Widen byte fields -> 16-bit fields for the final (max 256) round.
    unsigned e_lo = e & 0x00FF00FFu;           // [c0 | c4<<16]
    unsigned e_hi = (e >> 8) & 0x00FF00FFu;    // [c2 | c6<<16]
    unsigned o_lo = o & 0x00FF00FFu;           // [c1 | c5<<16]
    unsigned o_hi = (o >> 8) & 0x00FF00FFu;    // [c3 | c7<<16]
    e_lo += __shfl_xor_sync(0xffffffffu, e_lo, 2);
    e_hi += __shfl_xor_sync(0xffffffffu, e_hi, 2);
    o_lo += __shfl_xor_sync(0xffffffffu, o_lo, 2);
    o_hi += __shfl_xor_sync(0xffffffffu, o_hi, 2);

    if ((lane & 3) == 0) {
        int counts[8];
        counts[0] = e_lo & 0xFFFF;  counts[4] = e_lo >> 16;
        counts[2] = e_hi & 0xFFFF;  counts[6] = e_hi >> 16;
        counts[1] = o_lo & 0xFFFF;  counts[5] = o_lo >> 16;
        counts[3] = o_hi & 0xFFFF;  counts[7] = o_hi >> 16;

        int best = counts[0], arg = 0;
#pragma unroll
        for (int i = 1; i < 8; ++i) {
            if (counts[i] > best) { best = counts[i]; arg = i; }  // first-max
        }
        // ratio < 0.75  <=>  count < 192 (0.75 * 256 == 192 exactly)
        const int res = (arg == 7 || best < 192) ? -1 : arg;

        const int tw = (twg << 3) + (lane >> 2);
        out[b * TILES_PER_IMG + th * 64 + tw] = (float)res;
    }
}

extern "C" void kernel_launch(void* const* d_in, const int* in_sizes, int n_in,
                              void* d_out, int out_size) {
    const int* label = (const int*)d_in[0];
    float* out = (float*)d_out;

    // 8M px / 256 px per tile / 8 tiles per warp = 4096 warps.
    const int n_tiles = in_sizes[0] / (SCALE * SCALE);
    const int n_warps = n_tiles / 8;

    const int threads = 128;                 // 4 warps/block -> 1024 blocks
    const int blocks = (n_warps * 32 + threads - 1) / threads;

    downscale_label_kernel<<<blocks, threads>>>(label, out, n_warps);
}